// round 16
// baseline (speedup 1.0000x reference)
#include <cuda_runtime.h>
#include <cuda_bf16.h>
#include <stdint.h>

// Problem constants
#define BATCH   4
#define SEQ     2048
#define EMB     512
#define HEADS   8
#define DH      64
#define MROWS   (BATCH * SEQ)     // 8192
#define NQKV    (3 * EMB)         // 1536

// ======================= scratch (__device__ globals) =========================
__device__ __nv_bfloat16 g_qkvh[(size_t)MROWS * NQKV];
__device__ __nv_bfloat16 g_qkvl[(size_t)MROWS * NQKV];
__device__ float  g_y[(size_t)MROWS * EMB];
// int8 2-digit quantized operands + per-row scales
__device__ int8_t g_x1[(size_t)MROWS * EMB];
__device__ int8_t g_x2[(size_t)MROWS * EMB];
__device__ float  g_sx[MROWS];
__device__ int8_t g_y1[(size_t)MROWS * EMB];
__device__ int8_t g_y2[(size_t)MROWS * EMB];
__device__ float  g_sy[MROWS];
__device__ int8_t g_wa1[(size_t)NQKV * EMB];   // W_attn^T [1536,512]
__device__ int8_t g_wa2[(size_t)NQKV * EMB];
__device__ float  g_swa[NQKV];
__device__ int8_t g_wo1[(size_t)EMB * EMB];    // W_out^T [512,512]
__device__ int8_t g_wo2[(size_t)EMB * EMB];
__device__ float  g_swo[EMB];

// ======================= helpers ==============================================
__device__ __forceinline__ uint32_t smem_u32(const void* p) {
    uint32_t a;
    asm("{ .reg .u64 t; cvta.to.shared.u64 t, %1; cvt.u32.u64 %0, t; }" : "=r"(a) : "l"(p));
    return a;
}
__device__ __forceinline__ void cp16(uint32_t dst, const void* src) {
    asm volatile("cp.async.cg.shared.global [%0], [%1], 16;" :: "r"(dst), "l"(src));
}
#define CP_COMMIT() asm volatile("cp.async.commit_group;" ::: "memory")
#define CP_WAIT(n)  asm volatile("cp.async.wait_group %0;" :: "n"(n) : "memory")

__device__ __forceinline__ void ldsm_x4(uint32_t* r, uint32_t addr) {
    asm volatile("ldmatrix.sync.aligned.m8n8.x4.shared.b16 {%0,%1,%2,%3}, [%4];"
                 : "=r"(r[0]), "=r"(r[1]), "=r"(r[2]), "=r"(r[3]) : "r"(addr));
}
__device__ __forceinline__ void ldsm_x4_t(uint32_t* r, uint32_t addr) {
    asm volatile("ldmatrix.sync.aligned.m8n8.x4.trans.shared.b16 {%0,%1,%2,%3}, [%4];"
                 : "=r"(r[0]), "=r"(r[1]), "=r"(r[2]), "=r"(r[3]) : "r"(addr));
}
__device__ __forceinline__ void mma_bf16(float* c, const uint32_t* a, const uint32_t* b) {
    asm volatile("mma.sync.aligned.m16n8k16.row.col.f32.bf16.bf16.f32 "
                 "{%0,%1,%2,%3}, {%4,%5,%6,%7}, {%8,%9}, {%0,%1,%2,%3};"
                 : "+f"(c[0]), "+f"(c[1]), "+f"(c[2]), "+f"(c[3])
                 : "r"(a[0]), "r"(a[1]), "r"(a[2]), "r"(a[3]), "r"(b[0]), "r"(b[1]));
}
__device__ __forceinline__ void mma_s8(int* d, const uint32_t* a, const uint32_t* b) {
    asm volatile("mma.sync.aligned.m16n8k32.row.col.s32.s8.s8.s32 "
                 "{%0,%1,%2,%3}, {%4,%5,%6,%7}, {%8,%9}, {%0,%1,%2,%3};"
                 : "+r"(d[0]), "+r"(d[1]), "+r"(d[2]), "+r"(d[3])
                 : "r"(a[0]), "r"(a[1]), "r"(a[2]), "r"(a[3]), "r"(b[0]), "r"(b[1]));
}
__device__ __forceinline__ float ex2f(float x) {
    float y;
    asm("ex2.approx.f32 %0, %1;" : "=f"(y) : "f"(x));
    return y;
}
// split pair of fp32 into bf16 hi (packed) + bf16 lo residual (packed)
__device__ __forceinline__ void split2(float v0, float v1, uint32_t& hh, uint32_t& ll) {
    __nv_bfloat162 h2, l2;
    h2.x = __float2bfloat16(v0);
    h2.y = __float2bfloat16(v1);
    l2.x = __float2bfloat16(v0 - __bfloat162float(h2.x));
    l2.y = __float2bfloat16(v1 - __bfloat162float(h2.y));
    hh = *(uint32_t*)&h2;
    ll = *(uint32_t*)&l2;
}
__device__ __forceinline__ int8_t q8(float v) {
    float r = rintf(v);
    r = fminf(fmaxf(r, -127.0f), 127.0f);
    return (int8_t)(int)r;
}

// ======================= quantization kernels =================================
// per-row 2-digit int8 quantization of a [rows, 512] fp32 matrix; 1 warp/row
__global__ __launch_bounds__(256) void quant_rows(const float* __restrict__ in,
                                                  int8_t* __restrict__ d1,
                                                  int8_t* __restrict__ d2,
                                                  float* __restrict__ sc) {
    const int row = blockIdx.x * 8 + (threadIdx.x >> 5);
    const int lane = threadIdx.x & 31;
    const float4* r4 = (const float4*)(in + (size_t)row * EMB);
    float4 v[4];
    float mx = 0.0f;
#pragma unroll
    for (int i = 0; i < 4; i++) {
        v[i] = r4[lane + i * 32];
        mx = fmaxf(mx, fmaxf(fmaxf(fabsf(v[i].x), fabsf(v[i].y)),
                             fmaxf(fabsf(v[i].z), fabsf(v[i].w))));
    }
#pragma unroll
    for (int d = 16; d > 0; d >>= 1)
        mx = fmaxf(mx, __shfl_xor_sync(0xffffffffu, mx, d));
    float s = mx * (1.0f / 127.0f);
    if (s == 0.0f) s = 1.0f;
    const float inv = 1.0f / s;
    if (lane == 0) sc[row] = s;
#pragma unroll
    for (int i = 0; i < 4; i++) {
        const float* e = &v[i].x;
        char4 q1, q2;
        int8_t* p1 = (int8_t*)&q1;
        int8_t* p2 = (int8_t*)&q2;
#pragma unroll
        for (int j = 0; j < 4; j++) {
            float val = e[j];
            int8_t a1 = q8(val * inv);
            float rres = val - (float)a1 * s;
            p1[j] = a1;
            p2[j] = q8(rres * inv * 128.0f);
        }
        size_t off = (size_t)row * EMB + (lane + i * 32) * 4;
        *(char4*)(d1 + off) = q1;
        *(char4*)(d2 + off) = q2;
    }
}

// per-column absmax of W [K, N] -> scale[n]
__global__ __launch_bounds__(256) void wcol_absmax(const float* __restrict__ W,
                                                   float* __restrict__ sc,
                                                   int K, int N) {
    const int n = blockIdx.x * 8 + (threadIdx.x >> 5);
    const int lane = threadIdx.x & 31;
    if (n >= N) return;
    float mx = 0.0f;
    for (int k = lane; k < K; k += 32)
        mx = fmaxf(mx, fabsf(W[(size_t)k * N + n]));
#pragma unroll
    for (int d = 16; d > 0; d >>= 1)
        mx = fmaxf(mx, __shfl_xor_sync(0xffffffffu, mx, d));
    if (lane == 0) {
        float s = mx * (1.0f / 127.0f);
        sc[n] = (s == 0.0f) ? 1.0f : s;
    }
}

// W [K,N] -> W^T [N,K] 2-digit int8, 32x32 tiled transpose
__global__ __launch_bounds__(256) void conv_w_tq(const float* __restrict__ W,
                                                 int8_t* __restrict__ d1,
                                                 int8_t* __restrict__ d2,
                                                 const float* __restrict__ sc,
                                                 int K, int N) {
    __shared__ float tile[32][33];
    const int tx = threadIdx.x & 31, ty = threadIdx.x >> 5;
    const int n0 = blockIdx.x * 32, k0 = blockIdx.y * 32;
#pragma unroll
    for (int i = 0; i < 4; i++) {
        int k = k0 + ty + i * 8;
        tile[ty + i * 8][tx] = W[(size_t)k * N + n0 + tx];
    }
    __syncthreads();
#pragma unroll
    for (int i = 0; i < 4; i++) {
        int n = n0 + ty + i * 8;
        float s = sc[n];
        float inv = 1.0f / s;
        float v = tile[tx][ty + i * 8];
        int8_t a1 = q8(v * inv);
        float r = v - (float)a1 * s;
        size_t o = (size_t)n * K + k0 + tx;
        d1[o] = a1;
        d2[o] = q8(r * inv * 128.0f);
    }
}

// ======================= 2-digit int8 IMMA GEMM ===============================
// C[M,N] = sA_i*sB_j*(D1 + D2/128) + bias, D1=a1b1, D2=a1b2+a2b1 (int32 exact)
// BM=128, BN=128, BK=32, 512 threads (16 warps 4m x 4n, warp tile 32x32)
// smem/stage: A1(0) A2(6144) B1(12288) B2(18432); row stride 48B; 3 stages
#define GI_STAGE 24576
#define GI_SMEM  (3 * GI_STAGE)   // 73728

template<int OUT_SPLIT>
__global__ __launch_bounds__(512, 1) void igemm(
    const int8_t* __restrict__ A1, const int8_t* __restrict__ A2,
    const float* __restrict__ sA,
    const int8_t* __restrict__ B1, const int8_t* __restrict__ B2,
    const float* __restrict__ sB,
    const float* __restrict__ bias,
    float* __restrict__ C, __nv_bfloat16* __restrict__ Ch, __nv_bfloat16* __restrict__ Cl,
    int N, int K)
{
    extern __shared__ char smem[];
    const uint32_t sb = smem_u32(smem);
    const int tid = threadIdx.x;
    const int lane = tid & 31, wid = tid >> 5;
    const int bm = blockIdx.y * 128, bn = blockIdx.x * 128;
    const int wm = (wid >> 2) * 32, wn = (wid & 3) * 32;

    // ldmatrix lane geometry (16B units along k)
    const int a_row  = (lane & 7) + ((lane >> 3) & 1) * 8;
    const int a_hk16 = ((lane >> 4) & 1) * 16;          // k-half byte offset
    const int b_row  = (lane & 7) + ((lane >> 4) & 1) * 8;
    const int b_hk16 = ((lane >> 3) & 1) * 16;

    int d1[2][4][4], d2[2][4][4];
#pragma unroll
    for (int i = 0; i < 2; i++)
#pragma unroll
        for (int j = 0; j < 4; j++)
#pragma unroll
            for (int r = 0; r < 4; r++) { d1[i][j][r] = 0; d2[i][j][r] = 0; }

    const int nstage = K >> 5;   // k32 per stage

    // loader: A 512 slots, B 512 slots; 1 cp16 each per thread
    auto load_stage = [&](int k0, int buf) {
        const uint32_t s0 = sb + buf * GI_STAGE;
        {
            int row = tid >> 2, digit = (tid >> 1) & 1, half = tid & 1;
            uint32_t doff = s0 + digit * 6144 + row * 48 + half * 16;
            const int8_t* src = digit ? A2 : A1;
            cp16(doff, src + (size_t)(bm + row) * K + k0 + half * 16);
        }
        {
            int row = tid >> 2, digit = (tid >> 1) & 1, half = tid & 1;
            uint32_t doff = s0 + 12288 + digit * 6144 + row * 48 + half * 16;
            const int8_t* src = digit ? B2 : B1;
            cp16(doff, src + (size_t)(bn + row) * K + k0 + half * 16);
        }
    };

    load_stage(0, 0);
    CP_COMMIT();
    load_stage(32, 1);
    CP_COMMIT();

    for (int s = 0; s < nstage; s++) {
        if (s == nstage - 1) { CP_WAIT(0); } else { CP_WAIT(1); }
        __syncthreads();
        if (s + 2 < nstage) {
            load_stage((s + 2) * 32, (s + 2) % 3);
            CP_COMMIT();
        }
        const uint32_t s0 = sb + (s % 3) * GI_STAGE;

        // B fragments: 4 n8-blocks x 2 k-halves, both digits
        uint32_t b1f[4][2], b2f[4][2];
#pragma unroll
        for (int pr = 0; pr < 2; pr++) {
            uint32_t r4[4];
            uint32_t addr = s0 + 12288 + (uint32_t)(wn + pr * 16 + b_row) * 48 + b_hk16;
            ldsm_x4(r4, addr);
            b1f[pr * 2][0] = r4[0]; b1f[pr * 2][1] = r4[1];
            b1f[pr * 2 + 1][0] = r4[2]; b1f[pr * 2 + 1][1] = r4[3];
            ldsm_x4(r4, addr + 6144);
            b2f[pr * 2][0] = r4[0]; b2f[pr * 2][1] = r4[1];
            b2f[pr * 2 + 1][0] = r4[2]; b2f[pr * 2 + 1][1] = r4[3];
        }
        // A fragments: 2 m16 frags, both digits
        uint32_t a1f[2][4], a2f[2][4];
#pragma unroll
        for (int mf = 0; mf < 2; mf++) {
            uint32_t addr = s0 + (uint32_t)(wm + mf * 16 + a_row) * 48 + a_hk16;
            ldsm_x4(a1f[mf], addr);
            ldsm_x4(a2f[mf], addr + 6144);
        }
        // term-major: reuse gap = 8 MMAs per accumulator set
#pragma unroll
        for (int mf = 0; mf < 2; mf++)
#pragma unroll
            for (int nf = 0; nf < 4; nf++) mma_s8(d1[mf][nf], a1f[mf], b1f[nf]);
#pragma unroll
        for (int mf = 0; mf < 2; mf++)
#pragma unroll
            for (int nf = 0; nf < 4; nf++) mma_s8(d2[mf][nf], a1f[mf], b2f[nf]);
#pragma unroll
        for (int mf = 0; mf < 2; mf++)
#pragma unroll
            for (int nf = 0; nf < 4; nf++) mma_s8(d2[mf][nf], a2f[mf], b1f[nf]);
    }

    // epilogue: C = sa*sb*(D1 + D2/128) (+bias)
    const int trow = lane >> 2, tcol = (lane & 3) * 2;
#pragma unroll
    for (int mf = 0; mf < 2; mf++) {
        int row = bm + wm + mf * 16 + trow;
        float sa0 = sA[row], sa1 = sA[row + 8];
#pragma unroll
        for (int nf = 0; nf < 4; nf++) {
            int col = bn + wn + nf * 8 + tcol;
            float2 sbv = *(const float2*)(sB + col);
            float2 bs = *(const float2*)(bias + col);
            float v0 = sa0 * sbv.x * ((float)d1[mf][nf][0] + 0.0078125f * (float)d2[mf][nf][0]) + bs.x;
            float v1 = sa0 * sbv.y * ((float)d1[mf][nf][1] + 0.0078125f * (float)d2[mf][nf][1]) + bs.y;
            float v2 = sa1 * sbv.x * ((float)d1[mf][nf][2] + 0.0078125f * (float)d2[mf][nf][2]) + bs.x;
            float v3 = sa1 * sbv.y * ((float)d1[mf][nf][3] + 0.0078125f * (float)d2[mf][nf][3]) + bs.y;
            if (OUT_SPLIT) {
                uint32_t hh, ll;
                split2(v0, v1, hh, ll);
                *(uint32_t*)(Ch + (size_t)row * N + col) = hh;
                *(uint32_t*)(Cl + (size_t)row * N + col) = ll;
                split2(v2, v3, hh, ll);
                *(uint32_t*)(Ch + (size_t)(row + 8) * N + col) = hh;
                *(uint32_t*)(Cl + (size_t)(row + 8) * N + col) = ll;
            } else {
                float2 o0; o0.x = v0; o0.y = v1;
                float2 o1; o1.x = v2; o1.y = v3;
                *(float2*)(C + (size_t)row * N + col) = o0;
                *(float2*)(C + (size_t)(row + 8) * N + col) = o1;
            }
        }
    }
}

// ======================= HMMA flash attention (bf16 split, unchanged core) ====
#define FA_QBYTES 18432
#define FA_KVBUF  36864
#define FA_SMEM   (2 * FA_QBYTES + 2 * FA_KVBUF)   // 110592

__global__ __launch_bounds__(256, 2) void flash_hmma()
{
    extern __shared__ char smem[];
    const uint32_t sb = smem_u32(smem);
    const int tid = threadIdx.x;
    const int lane = tid & 31, wid = tid >> 5;
    const int qb = blockIdx.x * 128;
    const int h  = blockIdx.y;
    const int b  = blockIdx.z;
    const int wq = wid * 16;

    const size_t grow0 = (size_t)b * SEQ;
    const int qcol = h * DH;
    const int kcol = EMB + h * DH;
    const int vcol = 2 * EMB + h * DH;

#pragma unroll
    for (int i = 0; i < 4; i++) {
        int cidx = tid + i * 256;
        int row = cidx >> 3, kc = cidx & 7;
        uint32_t doff = row * 144 + kc * 16;
        size_t go = (grow0 + qb + row) * NQKV + qcol + kc * 8;
        cp16(sb + doff,             g_qkvh + go);
        cp16(sb + FA_QBYTES + doff, g_qkvl + go);
    }
    CP_COMMIT();

    auto load_kv = [&](int t, int buf) {
        const uint32_t kv = sb + 2 * FA_QBYTES + buf * FA_KVBUF;
#pragma unroll
        for (int i = 0; i < 2; i++) {
            int cidx = tid + i * 256;
            int row = cidx >> 3, kc = cidx & 7;
            uint32_t doff = row * 144 + kc * 16;
            size_t gk = (grow0 + t * 64 + row) * NQKV + kcol + kc * 8;
            size_t gv = (grow0 + t * 64 + row) * NQKV + vcol + kc * 8;
            cp16(kv + doff,         g_qkvh + gk);
            cp16(kv + 9216 + doff,  g_qkvl + gk);
            cp16(kv + 18432 + doff, g_qkvh + gv);
            cp16(kv + 27648 + doff, g_qkvl + gv);
        }
    };

    load_kv(0, 0);
    CP_COMMIT();

    CP_WAIT(1);
    __syncthreads();
    const int a_row = (lane & 7) + ((lane >> 3) & 1) * 8;
    const int a_kc  = ((lane >> 4) & 1) * 8;
    uint32_t qh_f[4][4], ql_f[4][4];
#pragma unroll
    for (int kc = 0; kc < 4; kc++) {
        uint32_t addr = sb + (uint32_t)(wq + a_row) * 144 + (kc * 16 + a_kc) * 2;
        ldsm_x4(qh_f[kc], addr);
        ldsm_x4(ql_f[kc], addr + FA_QBYTES);
    }

    const int bk_row = (lane & 7) + ((lane >> 4) & 1) * 8;
    const int bk_kc  = ((lane >> 3) & 1) * 8;
    const int v_row = (lane & 7) + ((lane >> 3) & 1) * 8;
    const int v_col = ((lane >> 4) & 1) * 8;

    float o[8][4];
#pragma unroll
    for (int i = 0; i < 8; i++)
#pragma unroll
        for (int r = 0; r < 4; r++) o[i][r] = 0.0f;
    float m0 = -1e30f, m1 = -1e30f, l0 = 0.0f, l1 = 0.0f;
    const float SCL = 0.1803368801111137f;   // 0.125 * log2(e)

    const int NT = SEQ / 64;
    for (int t = 0; t < NT; t++) {
        CP_WAIT(0);
        __syncthreads();
        if (t + 1 < NT) {
            load_kv(t + 1, (t + 1) & 1);
            CP_COMMIT();
        }
        const uint32_t kvb = sb + 2 * FA_QBYTES + (t & 1) * FA_KVBUF;

        float s[8][4];
#pragma unroll
        for (int i = 0; i < 8; i++)
#pragma unroll
            for (int r = 0; r < 4; r++) s[i][r] = 0.0f;
#pragma unroll
        for (int kc = 0; kc < 4; kc++) {
            uint32_t kf[4][4];
#pragma unroll
            for (int np = 0; np < 4; np++)
                ldsm_x4(kf[np], kvb + (uint32_t)(np * 16 + bk_row) * 144 + (kc * 16 + bk_kc) * 2);
#pragma unroll
            for (int np = 0; np < 4; np++) {
                mma_bf16(s[np * 2],     qh_f[kc], kf[np]);
                mma_bf16(s[np * 2 + 1], qh_f[kc], kf[np] + 2);
            }
#pragma unroll
            for (int np = 0; np < 4; np++) {
                mma_bf16(s[np * 2],     ql_f[kc], kf[np]);
                mma_bf16(s[np * 2 + 1], ql_f[kc], kf[np] + 2);
            }
#pragma unroll
            for (int np = 0; np < 4; np++)
                ldsm_x4(kf[np], kvb + 9216 + (uint32_t)(np * 16 + bk_row) * 144 + (kc * 16 + bk_kc) * 2);
#pragma unroll
            for (int np = 0; np < 4; np++) {
                mma_bf16(s[np * 2],     qh_f[kc], kf[np]);
                mma_bf16(s[np * 2 + 1], qh_f[kc], kf[np] + 2);
            }
        }

        float rm0 = -1e30f, rm1 = -1e30f;
#pragma unroll
        for (int nf = 0; nf < 8; nf++) {
            rm0 = fmaxf(rm0, fmaxf(s[nf][0], s[nf][1]));
            rm1 = fmaxf(rm1, fmaxf(s[nf][2], s[nf][3]));
        }
        rm0 = fmaxf(rm0, __shfl_xor_sync(0xffffffffu, rm0, 1));
        rm0 = fmaxf(rm0, __shfl_xor_sync(0xffffffffu, rm0, 2));
        rm1 = fmaxf(rm1, __shfl_xor_sync(0xffffffffu, rm1, 1));
        rm1 = fmaxf(rm1, __shfl_xor_sync(0xffffffffu, rm1, 2));
        float mn0 = fmaxf(m0, rm0 * SCL);
        float mn1 = fmaxf(m1, rm1 * SCL);
        float corr0 = ex2f(m0 - mn0);
        float corr1 = ex2f(m1 - mn1);
        m0 = mn0; m1 = mn1;
        float sum0 = 0.0f, sum1 = 0.0f;
#pragma unroll
        for (int nf = 0; nf < 8; nf++) {
            s[nf][0] = ex2f(fmaf(s[nf][0], SCL, -mn0));
            s[nf][1] = ex2f(fmaf(s[nf][1], SCL, -mn0));
            s[nf][2] = ex2f(fmaf(s[nf][2], SCL, -mn1));
            s[nf][3] = ex2f(fmaf(s[nf][3], SCL, -mn1));
            sum0 += s[nf][0] + s[nf][1];
            sum1 += s[nf][2] + s[nf][3];
        }
        sum0 += __shfl_xor_sync(0xffffffffu, sum0, 1);
        sum0 += __shfl_xor_sync(0xffffffffu, sum0, 2);
        sum1 += __shfl_xor_sync(0xffffffffu, sum1, 1);
        sum1 += __shfl_xor_sync(0xffffffffu, sum1, 2);
        l0 = l0 * corr0 + sum0;
        l1 = l1 * corr1 + sum1;
#pragma unroll
        for (int nf = 0; nf < 8; nf++) {
            o[nf][0] *= corr0; o[nf][1] *= corr0;
            o[nf][2] *= corr1; o[nf][3] *= corr1;
        }
        uint32_t ph[4][4], pl[4][4];
#pragma unroll
        for (int kc = 0; kc < 4; kc++) {
            split2(s[2 * kc][0],     s[2 * kc][1],     ph[kc][0], pl[kc][0]);
            split2(s[2 * kc][2],     s[2 * kc][3],     ph[kc][1], pl[kc][1]);
            split2(s[2 * kc + 1][0], s[2 * kc + 1][1], ph[kc][2], pl[kc][2]);
            split2(s[2 * kc + 1][2], s[2 * kc + 1][3], ph[kc][3], pl[kc][3]);
        }

#pragma unroll
        for (int kc = 0; kc < 4; kc++) {
            uint32_t vf[4][4];
#pragma unroll
            for (int np = 0; np < 4; np++)
                ldsm_x4_t(vf[np], kvb + 18432 + (uint32_t)(kc * 16 + v_row) * 144 + (np * 16 + v_col) * 2);
#pragma unroll
            for (int np = 0; np < 4; np++) {
                mma_bf16(o[np * 2],     ph[kc], vf[np]);
                mma_bf16(o[np * 2 + 1], ph[kc], vf[np] + 2);
            }
#pragma unroll
            for (int np = 0; np < 4; np++) {
                mma_bf16(o[np * 2],     pl[kc], vf[np]);
                mma_bf16(o[np * 2 + 1], pl[kc], vf[np] + 2);
            }
#pragma unroll
            for (int np = 0; np < 4; np++)
                ldsm_x4_t(vf[np], kvb + 27648 + (uint32_t)(kc * 16 + v_row) * 144 + (np * 16 + v_col) * 2);
#pragma unroll
            for (int np = 0; np < 4; np++) {
                mma_bf16(o[np * 2],     ph[kc], vf[np]);
                mma_bf16(o[np * 2 + 1], ph[kc], vf[np] + 2);
            }
        }
    }

    // ---- epilogue: normalize, write fp32 y (quantized by a later pass) ----
    float inv0 = 1.0f / l0, inv1 = 1.0f / l1;
    size_t row0 = grow0 + qb + wq + (lane >> 2);
#pragma unroll
    for (int nf = 0; nf < 8; nf++) {
        int col = h * DH + nf * 8 + (lane & 3) * 2;
        float2 y0; y0.x = o[nf][0] * inv0; y0.y = o[nf][1] * inv0;
        float2 y1; y1.x = o[nf][2] * inv1; y1.y = o[nf][3] * inv1;
        *(float2*)(g_y + row0 * EMB + col) = y0;
        *(float2*)(g_y + (row0 + 8) * EMB + col) = y1;
    }
}

// ======================= launch ===============================================
extern "C" void kernel_launch(void* const* d_in, const int* in_sizes, int n_in,
                              void* d_out, int out_size)
{
    const float* x  = (const float*)d_in[0];
    const float* Wa = (const float*)d_in[1];
    const float* ba = (const float*)d_in[2];
    const float* Wo = (const float*)d_in[3];
    const float* bo = (const float*)d_in[4];
    float* out = (float*)d_out;

    cudaFuncSetAttribute(igemm<1>, cudaFuncAttributeMaxDynamicSharedMemorySize, GI_SMEM);
    cudaFuncSetAttribute(igemm<0>, cudaFuncAttributeMaxDynamicSharedMemorySize, GI_SMEM);
    cudaFuncSetAttribute(flash_hmma, cudaFuncAttributeMaxDynamicSharedMemorySize, FA_SMEM);

    __nv_bfloat16 *qh, *ql;
    float *y, *sx, *sy, *swa, *swo;
    int8_t *x1, *x2, *y1, *y2, *wa1, *wa2, *wo1, *wo2;
    cudaGetSymbolAddress((void**)&qh,  g_qkvh);
    cudaGetSymbolAddress((void**)&ql,  g_qkvl);
    cudaGetSymbolAddress((void**)&y,   g_y);
    cudaGetSymbolAddress((void**)&x1,  g_x1);
    cudaGetSymbolAddress((void**)&x2,  g_x2);
    cudaGetSymbolAddress((void**)&sx,  g_sx);
    cudaGetSymbolAddress((void**)&y1,  g_y1);
    cudaGetSymbolAddress((void**)&y2,  g_y2);
    cudaGetSymbolAddress((void**)&sy,  g_sy);
    cudaGetSymbolAddress((void**)&wa1, g_wa1);
    cudaGetSymbolAddress((void**)&wa2, g_wa2);
    cudaGetSymbolAddress((void**)&swa, g_swa);
    cudaGetSymbolAddress((void**)&wo1, g_wo1);
    cudaGetSymbolAddress((void**)&wo2, g_wo2);
    cudaGetSymbolAddress((void**)&swo, g_swo);

    // quantize inputs + weights
    quant_rows<<<MROWS / 8, 256>>>(x, x1, x2, sx);
    wcol_absmax<<<NQKV / 8, 256>>>(Wa, swa, EMB, NQKV);
    wcol_absmax<<<EMB / 8, 256>>>(Wo, swo, EMB, EMB);
    {
        dim3 gt(NQKV / 32, EMB / 32);
        conv_w_tq<<<gt, 256>>>(Wa, wa1, wa2, swa, EMB, NQKV);
        dim3 gt2(EMB / 32, EMB / 32);
        conv_w_tq<<<gt2, 256>>>(Wo, wo1, wo2, swo, EMB, EMB);
    }

    // QKV projection (int8 IMMA) -> bf16 hi/lo for flash
    dim3 g1(NQKV / 128, MROWS / 128);   // (12, 64)
    igemm<1><<<g1, 512, GI_SMEM>>>(x1, x2, sx, wa1, wa2, swa, ba,
                                   nullptr, qh, ql, NQKV, EMB);

    // attention (bf16 split HMMA) -> fp32 y
    dim3 g2(SEQ / 128, HEADS, BATCH);   // (16, 8, 4)
    flash_hmma<<<g2, 256, FA_SMEM>>>();

    // quantize y, output projection (int8 IMMA) -> fp32 out
    quant_rows<<<MROWS / 8, 256>>>(y, y1, y2, sy);
    dim3 g3(EMB / 128, MROWS / 128);    // (4, 64)
    igemm<0><<<g3, 512, GI_SMEM>>>(y1, y2, sy, wo1, wo2, swo, bo,
                                   out, nullptr, nullptr, EMB, EMB);
}

// round 17
// speedup vs baseline: 1.0006x; 1.0006x over previous
#include <cuda_runtime.h>
#include <cuda_bf16.h>
#include <stdint.h>

// Problem constants
#define BATCH   4
#define SEQ     2048
#define EMB     512
#define HEADS   8
#define DH      64
#define MROWS   (BATCH * SEQ)     // 8192
#define NQKV    (3 * EMB)         // 1536

// ======================= scratch (__device__ globals) =========================
__device__ __nv_bfloat16 g_qkvh[(size_t)MROWS * NQKV];
__device__ __nv_bfloat16 g_qkvl[(size_t)MROWS * NQKV];
__device__ float  g_y[(size_t)MROWS * EMB];
// int8 2-digit quantized operands + per-row scales
__device__ int8_t g_x1[(size_t)MROWS * EMB];
__device__ int8_t g_x2[(size_t)MROWS * EMB];
__device__ float  g_sx[MROWS];
__device__ int8_t g_y1[(size_t)MROWS * EMB];
__device__ int8_t g_y2[(size_t)MROWS * EMB];
__device__ float  g_sy[MROWS];
__device__ int8_t g_wa1[(size_t)NQKV * EMB];   // W_attn^T [1536,512]
__device__ int8_t g_wa2[(size_t)NQKV * EMB];
__device__ float  g_swa[NQKV];
__device__ int8_t g_wo1[(size_t)EMB * EMB];    // W_out^T [512,512]
__device__ int8_t g_wo2[(size_t)EMB * EMB];
__device__ float  g_swo[EMB];

// ======================= helpers ==============================================
__device__ __forceinline__ uint32_t smem_u32(const void* p) {
    uint32_t a;
    asm("{ .reg .u64 t; cvta.to.shared.u64 t, %1; cvt.u32.u64 %0, t; }" : "=r"(a) : "l"(p));
    return a;
}
__device__ __forceinline__ void cp16(uint32_t dst, const void* src) {
    asm volatile("cp.async.cg.shared.global [%0], [%1], 16;" :: "r"(dst), "l"(src));
}
#define CP_COMMIT() asm volatile("cp.async.commit_group;" ::: "memory")
#define CP_WAIT(n)  asm volatile("cp.async.wait_group %0;" :: "n"(n) : "memory")

__device__ __forceinline__ void ldsm_x4(uint32_t* r, uint32_t addr) {
    asm volatile("ldmatrix.sync.aligned.m8n8.x4.shared.b16 {%0,%1,%2,%3}, [%4];"
                 : "=r"(r[0]), "=r"(r[1]), "=r"(r[2]), "=r"(r[3]) : "r"(addr));
}
__device__ __forceinline__ void ldsm_x4_t(uint32_t* r, uint32_t addr) {
    asm volatile("ldmatrix.sync.aligned.m8n8.x4.trans.shared.b16 {%0,%1,%2,%3}, [%4];"
                 : "=r"(r[0]), "=r"(r[1]), "=r"(r[2]), "=r"(r[3]) : "r"(addr));
}
__device__ __forceinline__ void mma_bf16(float* c, const uint32_t* a, const uint32_t* b) {
    asm volatile("mma.sync.aligned.m16n8k16.row.col.f32.bf16.bf16.f32 "
                 "{%0,%1,%2,%3}, {%4,%5,%6,%7}, {%8,%9}, {%0,%1,%2,%3};"
                 : "+f"(c[0]), "+f"(c[1]), "+f"(c[2]), "+f"(c[3])
                 : "r"(a[0]), "r"(a[1]), "r"(a[2]), "r"(a[3]), "r"(b[0]), "r"(b[1]));
}
__device__ __forceinline__ void mma_s8(int* d, const uint32_t* a, const uint32_t* b) {
    asm volatile("mma.sync.aligned.m16n8k32.row.col.s32.s8.s8.s32 "
                 "{%0,%1,%2,%3}, {%4,%5,%6,%7}, {%8,%9}, {%0,%1,%2,%3};"
                 : "+r"(d[0]), "+r"(d[1]), "+r"(d[2]), "+r"(d[3])
                 : "r"(a[0]), "r"(a[1]), "r"(a[2]), "r"(a[3]), "r"(b[0]), "r"(b[1]));
}
__device__ __forceinline__ float ex2f(float x) {
    float y;
    asm("ex2.approx.f32 %0, %1;" : "=f"(y) : "f"(x));
    return y;
}
// split pair of fp32 into bf16 hi (packed) + bf16 lo residual (packed)
__device__ __forceinline__ void split2(float v0, float v1, uint32_t& hh, uint32_t& ll) {
    __nv_bfloat162 h2, l2;
    h2.x = __float2bfloat16(v0);
    h2.y = __float2bfloat16(v1);
    l2.x = __float2bfloat16(v0 - __bfloat162float(h2.x));
    l2.y = __float2bfloat16(v1 - __bfloat162float(h2.y));
    hh = *(uint32_t*)&h2;
    ll = *(uint32_t*)&l2;
}
__device__ __forceinline__ int8_t q8(float v) {
    float r = rintf(v);
    r = fminf(fmaxf(r, -127.0f), 127.0f);
    return (int8_t)(int)r;
}

// ======================= quantization kernels =================================
// per-row 2-digit int8 quantization of a [rows, 512] fp32 matrix; 1 warp/row
__global__ __launch_bounds__(256) void quant_rows(const float* __restrict__ in,
                                                  int8_t* __restrict__ d1,
                                                  int8_t* __restrict__ d2,
                                                  float* __restrict__ sc) {
    const int row = blockIdx.x * 8 + (threadIdx.x >> 5);
    const int lane = threadIdx.x & 31;
    const float4* r4 = (const float4*)(in + (size_t)row * EMB);
    float4 v[4];
    float mx = 0.0f;
#pragma unroll
    for (int i = 0; i < 4; i++) {
        v[i] = r4[lane + i * 32];
        mx = fmaxf(mx, fmaxf(fmaxf(fabsf(v[i].x), fabsf(v[i].y)),
                             fmaxf(fabsf(v[i].z), fabsf(v[i].w))));
    }
#pragma unroll
    for (int d = 16; d > 0; d >>= 1)
        mx = fmaxf(mx, __shfl_xor_sync(0xffffffffu, mx, d));
    float s = mx * (1.0f / 127.0f);
    if (s == 0.0f) s = 1.0f;
    const float inv = 1.0f / s;
    if (lane == 0) sc[row] = s;
#pragma unroll
    for (int i = 0; i < 4; i++) {
        const float* e = &v[i].x;
        char4 q1, q2;
        int8_t* p1 = (int8_t*)&q1;
        int8_t* p2 = (int8_t*)&q2;
#pragma unroll
        for (int j = 0; j < 4; j++) {
            float val = e[j];
            int8_t a1 = q8(val * inv);
            float rres = val - (float)a1 * s;
            p1[j] = a1;
            p2[j] = q8(rres * inv * 128.0f);
        }
        size_t off = (size_t)row * EMB + (lane + i * 32) * 4;
        *(char4*)(d1 + off) = q1;
        *(char4*)(d2 + off) = q2;
    }
}

// per-column absmax of W [K, N] -> scale[n]
__global__ __launch_bounds__(256) void wcol_absmax(const float* __restrict__ W,
                                                   float* __restrict__ sc,
                                                   int K, int N) {
    const int n = blockIdx.x * 8 + (threadIdx.x >> 5);
    const int lane = threadIdx.x & 31;
    if (n >= N) return;
    float mx = 0.0f;
    for (int k = lane; k < K; k += 32)
        mx = fmaxf(mx, fabsf(W[(size_t)k * N + n]));
#pragma unroll
    for (int d = 16; d > 0; d >>= 1)
        mx = fmaxf(mx, __shfl_xor_sync(0xffffffffu, mx, d));
    if (lane == 0) {
        float s = mx * (1.0f / 127.0f);
        sc[n] = (s == 0.0f) ? 1.0f : s;
    }
}

// W [K,N] -> W^T [N,K] 2-digit int8, 32x32 tiled transpose
__global__ __launch_bounds__(256) void conv_w_tq(const float* __restrict__ W,
                                                 int8_t* __restrict__ d1,
                                                 int8_t* __restrict__ d2,
                                                 const float* __restrict__ sc,
                                                 int K, int N) {
    __shared__ float tile[32][33];
    const int tx = threadIdx.x & 31, ty = threadIdx.x >> 5;
    const int n0 = blockIdx.x * 32, k0 = blockIdx.y * 32;
#pragma unroll
    for (int i = 0; i < 4; i++) {
        int k = k0 + ty + i * 8;
        tile[ty + i * 8][tx] = W[(size_t)k * N + n0 + tx];
    }
    __syncthreads();
#pragma unroll
    for (int i = 0; i < 4; i++) {
        int n = n0 + ty + i * 8;
        float s = sc[n];
        float inv = 1.0f / s;
        float v = tile[tx][ty + i * 8];
        int8_t a1 = q8(v * inv);
        float r = v - (float)a1 * s;
        size_t o = (size_t)n * K + k0 + tx;
        d1[o] = a1;
        d2[o] = q8(r * inv * 128.0f);
    }
}

// ======================= 2-digit int8 IMMA GEMM ===============================
// C[M,N] = sA_i*sB_j*(D1 + D2/128) + bias, D1=a1b1, D2=a1b2+a2b1 (int32 exact)
// BM=128, BN=128, BK=32, 512 threads (16 warps 4m x 4n, warp tile 32x32)
// smem/stage: A1(0) A2(6144) B1(12288) B2(18432); row stride 48B; 3 stages
#define GI_STAGE 24576
#define GI_SMEM  (3 * GI_STAGE)   // 73728

template<int OUT_SPLIT>
__global__ __launch_bounds__(512, 1) void igemm(
    const int8_t* __restrict__ A1, const int8_t* __restrict__ A2,
    const float* __restrict__ sA,
    const int8_t* __restrict__ B1, const int8_t* __restrict__ B2,
    const float* __restrict__ sB,
    const float* __restrict__ bias,
    float* __restrict__ C, __nv_bfloat16* __restrict__ Ch, __nv_bfloat16* __restrict__ Cl,
    int N, int K)
{
    extern __shared__ char smem[];
    const uint32_t sb = smem_u32(smem);
    const int tid = threadIdx.x;
    const int lane = tid & 31, wid = tid >> 5;
    const int bm = blockIdx.y * 128, bn = blockIdx.x * 128;
    const int wm = (wid >> 2) * 32, wn = (wid & 3) * 32;

    // ldmatrix lane geometry (16B units along k)
    const int a_row  = (lane & 7) + ((lane >> 3) & 1) * 8;
    const int a_hk16 = ((lane >> 4) & 1) * 16;          // k-half byte offset
    const int b_row  = (lane & 7) + ((lane >> 4) & 1) * 8;
    const int b_hk16 = ((lane >> 3) & 1) * 16;

    int d1[2][4][4], d2[2][4][4];
#pragma unroll
    for (int i = 0; i < 2; i++)
#pragma unroll
        for (int j = 0; j < 4; j++)
#pragma unroll
            for (int r = 0; r < 4; r++) { d1[i][j][r] = 0; d2[i][j][r] = 0; }

    const int nstage = K >> 5;   // k32 per stage

    // loader: A 512 slots, B 512 slots; 1 cp16 each per thread
    auto load_stage = [&](int k0, int buf) {
        const uint32_t s0 = sb + buf * GI_STAGE;
        {
            int row = tid >> 2, digit = (tid >> 1) & 1, half = tid & 1;
            uint32_t doff = s0 + digit * 6144 + row * 48 + half * 16;
            const int8_t* src = digit ? A2 : A1;
            cp16(doff, src + (size_t)(bm + row) * K + k0 + half * 16);
        }
        {
            int row = tid >> 2, digit = (tid >> 1) & 1, half = tid & 1;
            uint32_t doff = s0 + 12288 + digit * 6144 + row * 48 + half * 16;
            const int8_t* src = digit ? B2 : B1;
            cp16(doff, src + (size_t)(bn + row) * K + k0 + half * 16);
        }
    };

    load_stage(0, 0);
    CP_COMMIT();
    load_stage(32, 1);
    CP_COMMIT();

    for (int s = 0; s < nstage; s++) {
        if (s == nstage - 1) { CP_WAIT(0); } else { CP_WAIT(1); }
        __syncthreads();
        if (s + 2 < nstage) {
            load_stage((s + 2) * 32, (s + 2) % 3);
            CP_COMMIT();
        }
        const uint32_t s0 = sb + (s % 3) * GI_STAGE;

        // B fragments: 4 n8-blocks x 2 k-halves, both digits
        uint32_t b1f[4][2], b2f[4][2];
#pragma unroll
        for (int pr = 0; pr < 2; pr++) {
            uint32_t r4[4];
            uint32_t addr = s0 + 12288 + (uint32_t)(wn + pr * 16 + b_row) * 48 + b_hk16;
            ldsm_x4(r4, addr);
            b1f[pr * 2][0] = r4[0]; b1f[pr * 2][1] = r4[1];
            b1f[pr * 2 + 1][0] = r4[2]; b1f[pr * 2 + 1][1] = r4[3];
            ldsm_x4(r4, addr + 6144);
            b2f[pr * 2][0] = r4[0]; b2f[pr * 2][1] = r4[1];
            b2f[pr * 2 + 1][0] = r4[2]; b2f[pr * 2 + 1][1] = r4[3];
        }
        // A fragments: 2 m16 frags, both digits
        uint32_t a1f[2][4], a2f[2][4];
#pragma unroll
        for (int mf = 0; mf < 2; mf++) {
            uint32_t addr = s0 + (uint32_t)(wm + mf * 16 + a_row) * 48 + a_hk16;
            ldsm_x4(a1f[mf], addr);
            ldsm_x4(a2f[mf], addr + 6144);
        }
        // term-major: reuse gap = 8 MMAs per accumulator set
#pragma unroll
        for (int mf = 0; mf < 2; mf++)
#pragma unroll
            for (int nf = 0; nf < 4; nf++) mma_s8(d1[mf][nf], a1f[mf], b1f[nf]);
#pragma unroll
        for (int mf = 0; mf < 2; mf++)
#pragma unroll
            for (int nf = 0; nf < 4; nf++) mma_s8(d2[mf][nf], a1f[mf], b2f[nf]);
#pragma unroll
        for (int mf = 0; mf < 2; mf++)
#pragma unroll
            for (int nf = 0; nf < 4; nf++) mma_s8(d2[mf][nf], a2f[mf], b1f[nf]);
    }

    // epilogue: C = sa*sb*(D1 + D2/128) (+bias)
    const int trow = lane >> 2, tcol = (lane & 3) * 2;
#pragma unroll
    for (int mf = 0; mf < 2; mf++) {
        int row = bm + wm + mf * 16 + trow;
        float sa0 = sA[row], sa1 = sA[row + 8];
#pragma unroll
        for (int nf = 0; nf < 4; nf++) {
            int col = bn + wn + nf * 8 + tcol;
            float2 sbv = *(const float2*)(sB + col);
            float2 bs = *(const float2*)(bias + col);
            float v0 = sa0 * sbv.x * ((float)d1[mf][nf][0] + 0.0078125f * (float)d2[mf][nf][0]) + bs.x;
            float v1 = sa0 * sbv.y * ((float)d1[mf][nf][1] + 0.0078125f * (float)d2[mf][nf][1]) + bs.y;
            float v2 = sa1 * sbv.x * ((float)d1[mf][nf][2] + 0.0078125f * (float)d2[mf][nf][2]) + bs.x;
            float v3 = sa1 * sbv.y * ((float)d1[mf][nf][3] + 0.0078125f * (float)d2[mf][nf][3]) + bs.y;
            if (OUT_SPLIT) {
                uint32_t hh, ll;
                split2(v0, v1, hh, ll);
                *(uint32_t*)(Ch + (size_t)row * N + col) = hh;
                *(uint32_t*)(Cl + (size_t)row * N + col) = ll;
                split2(v2, v3, hh, ll);
                *(uint32_t*)(Ch + (size_t)(row + 8) * N + col) = hh;
                *(uint32_t*)(Cl + (size_t)(row + 8) * N + col) = ll;
            } else {
                float2 o0; o0.x = v0; o0.y = v1;
                float2 o1; o1.x = v2; o1.y = v3;
                *(float2*)(C + (size_t)row * N + col) = o0;
                *(float2*)(C + (size_t)(row + 8) * N + col) = o1;
            }
        }
    }
}

// ======================= HMMA flash attention (bf16 split, unchanged core) ====
#define FA_QBYTES 18432
#define FA_KVBUF  36864
#define FA_SMEM   (2 * FA_QBYTES + 2 * FA_KVBUF)   // 110592

__global__ __launch_bounds__(256, 2) void flash_hmma()
{
    extern __shared__ char smem[];
    const uint32_t sb = smem_u32(smem);
    const int tid = threadIdx.x;
    const int lane = tid & 31, wid = tid >> 5;
    const int qb = blockIdx.x * 128;
    const int h  = blockIdx.y;
    const int b  = blockIdx.z;
    const int wq = wid * 16;

    const size_t grow0 = (size_t)b * SEQ;
    const int qcol = h * DH;
    const int kcol = EMB + h * DH;
    const int vcol = 2 * EMB + h * DH;

#pragma unroll
    for (int i = 0; i < 4; i++) {
        int cidx = tid + i * 256;
        int row = cidx >> 3, kc = cidx & 7;
        uint32_t doff = row * 144 + kc * 16;
        size_t go = (grow0 + qb + row) * NQKV + qcol + kc * 8;
        cp16(sb + doff,             g_qkvh + go);
        cp16(sb + FA_QBYTES + doff, g_qkvl + go);
    }
    CP_COMMIT();

    auto load_kv = [&](int t, int buf) {
        const uint32_t kv = sb + 2 * FA_QBYTES + buf * FA_KVBUF;
#pragma unroll
        for (int i = 0; i < 2; i++) {
            int cidx = tid + i * 256;
            int row = cidx >> 3, kc = cidx & 7;
            uint32_t doff = row * 144 + kc * 16;
            size_t gk = (grow0 + t * 64 + row) * NQKV + kcol + kc * 8;
            size_t gv = (grow0 + t * 64 + row) * NQKV + vcol + kc * 8;
            cp16(kv + doff,         g_qkvh + gk);
            cp16(kv + 9216 + doff,  g_qkvl + gk);
            cp16(kv + 18432 + doff, g_qkvh + gv);
            cp16(kv + 27648 + doff, g_qkvl + gv);
        }
    };

    load_kv(0, 0);
    CP_COMMIT();

    CP_WAIT(1);
    __syncthreads();
    const int a_row = (lane & 7) + ((lane >> 3) & 1) * 8;
    const int a_kc  = ((lane >> 4) & 1) * 8;
    uint32_t qh_f[4][4], ql_f[4][4];
#pragma unroll
    for (int kc = 0; kc < 4; kc++) {
        uint32_t addr = sb + (uint32_t)(wq + a_row) * 144 + (kc * 16 + a_kc) * 2;
        ldsm_x4(qh_f[kc], addr);
        ldsm_x4(ql_f[kc], addr + FA_QBYTES);
    }

    const int bk_row = (lane & 7) + ((lane >> 4) & 1) * 8;
    const int bk_kc  = ((lane >> 3) & 1) * 8;
    const int v_row = (lane & 7) + ((lane >> 3) & 1) * 8;
    const int v_col = ((lane >> 4) & 1) * 8;

    float o[8][4];
#pragma unroll
    for (int i = 0; i < 8; i++)
#pragma unroll
        for (int r = 0; r < 4; r++) o[i][r] = 0.0f;
    float m0 = -1e30f, m1 = -1e30f, l0 = 0.0f, l1 = 0.0f;
    const float SCL = 0.1803368801111137f;   // 0.125 * log2(e)

    const int NT = SEQ / 64;
    for (int t = 0; t < NT; t++) {
        CP_WAIT(0);
        __syncthreads();
        if (t + 1 < NT) {
            load_kv(t + 1, (t + 1) & 1);
            CP_COMMIT();
        }
        const uint32_t kvb = sb + 2 * FA_QBYTES + (t & 1) * FA_KVBUF;

        float s[8][4];
#pragma unroll
        for (int i = 0; i < 8; i++)
#pragma unroll
            for (int r = 0; r < 4; r++) s[i][r] = 0.0f;
#pragma unroll
        for (int kc = 0; kc < 4; kc++) {
            uint32_t kf[4][4];
#pragma unroll
            for (int np = 0; np < 4; np++)
                ldsm_x4(kf[np], kvb + (uint32_t)(np * 16 + bk_row) * 144 + (kc * 16 + bk_kc) * 2);
#pragma unroll
            for (int np = 0; np < 4; np++) {
                mma_bf16(s[np * 2],     qh_f[kc], kf[np]);
                mma_bf16(s[np * 2 + 1], qh_f[kc], kf[np] + 2);
            }
#pragma unroll
            for (int np = 0; np < 4; np++) {
                mma_bf16(s[np * 2],     ql_f[kc], kf[np]);
                mma_bf16(s[np * 2 + 1], ql_f[kc], kf[np] + 2);
            }
#pragma unroll
            for (int np = 0; np < 4; np++)
                ldsm_x4(kf[np], kvb + 9216 + (uint32_t)(np * 16 + bk_row) * 144 + (kc * 16 + bk_kc) * 2);
#pragma unroll
            for (int np = 0; np < 4; np++) {
                mma_bf16(s[np * 2],     qh_f[kc], kf[np]);
                mma_bf16(s[np * 2 + 1], qh_f[kc], kf[np] + 2);
            }
        }

        float rm0 = -1e30f, rm1 = -1e30f;
#pragma unroll
        for (int nf = 0; nf < 8; nf++) {
            rm0 = fmaxf(rm0, fmaxf(s[nf][0], s[nf][1]));
            rm1 = fmaxf(rm1, fmaxf(s[nf][2], s[nf][3]));
        }
        rm0 = fmaxf(rm0, __shfl_xor_sync(0xffffffffu, rm0, 1));
        rm0 = fmaxf(rm0, __shfl_xor_sync(0xffffffffu, rm0, 2));
        rm1 = fmaxf(rm1, __shfl_xor_sync(0xffffffffu, rm1, 1));
        rm1 = fmaxf(rm1, __shfl_xor_sync(0xffffffffu, rm1, 2));
        float mn0 = fmaxf(m0, rm0 * SCL);
        float mn1 = fmaxf(m1, rm1 * SCL);
        float corr0 = ex2f(m0 - mn0);
        float corr1 = ex2f(m1 - mn1);
        m0 = mn0; m1 = mn1;
        float sum0 = 0.0f, sum1 = 0.0f;
#pragma unroll
        for (int nf = 0; nf < 8; nf++) {
            s[nf][0] = ex2f(fmaf(s[nf][0], SCL, -mn0));
            s[nf][1] = ex2f(fmaf(s[nf][1], SCL, -mn0));
            s[nf][2] = ex2f(fmaf(s[nf][2], SCL, -mn1));
            s[nf][3] = ex2f(fmaf(s[nf][3], SCL, -mn1));
            sum0 += s[nf][0] + s[nf][1];
            sum1 += s[nf][2] + s[nf][3];
        }
        sum0 += __shfl_xor_sync(0xffffffffu, sum0, 1);
        sum0 += __shfl_xor_sync(0xffffffffu, sum0, 2);
        sum1 += __shfl_xor_sync(0xffffffffu, sum1, 1);
        sum1 += __shfl_xor_sync(0xffffffffu, sum1, 2);
        l0 = l0 * corr0 + sum0;
        l1 = l1 * corr1 + sum1;
#pragma unroll
        for (int nf = 0; nf < 8; nf++) {
            o[nf][0] *= corr0; o[nf][1] *= corr0;
            o[nf][2] *= corr1; o[nf][3] *= corr1;
        }
        uint32_t ph[4][4], pl[4][4];
#pragma unroll
        for (int kc = 0; kc < 4; kc++) {
            split2(s[2 * kc][0],     s[2 * kc][1],     ph[kc][0], pl[kc][0]);
            split2(s[2 * kc][2],     s[2 * kc][3],     ph[kc][1], pl[kc][1]);
            split2(s[2 * kc + 1][0], s[2 * kc + 1][1], ph[kc][2], pl[kc][2]);
            split2(s[2 * kc + 1][2], s[2 * kc + 1][3], ph[kc][3], pl[kc][3]);
        }

#pragma unroll
        for (int kc = 0; kc < 4; kc++) {
            uint32_t vf[4][4];
#pragma unroll
            for (int np = 0; np < 4; np++)
                ldsm_x4_t(vf[np], kvb + 18432 + (uint32_t)(kc * 16 + v_row) * 144 + (np * 16 + v_col) * 2);
#pragma unroll
            for (int np = 0; np < 4; np++) {
                mma_bf16(o[np * 2],     ph[kc], vf[np]);
                mma_bf16(o[np * 2 + 1], ph[kc], vf[np] + 2);
            }
#pragma unroll
            for (int np = 0; np < 4; np++) {
                mma_bf16(o[np * 2],     pl[kc], vf[np]);
                mma_bf16(o[np * 2 + 1], pl[kc], vf[np] + 2);
            }
#pragma unroll
            for (int np = 0; np < 4; np++)
                ldsm_x4_t(vf[np], kvb + 27648 + (uint32_t)(kc * 16 + v_row) * 144 + (np * 16 + v_col) * 2);
#pragma unroll
            for (int np = 0; np < 4; np++) {
                mma_bf16(o[np * 2],     ph[kc], vf[np]);
                mma_bf16(o[np * 2 + 1], ph[kc], vf[np] + 2);
            }
        }
    }

    // ---- epilogue: normalize, write fp32 y (quantized by a later pass) ----
    float inv0 = 1.0f / l0, inv1 = 1.0f / l1;
    size_t row0 = grow0 + qb + wq + (lane >> 2);
#pragma unroll
    for (int nf = 0; nf < 8; nf++) {
        int col = h * DH + nf * 8 + (lane & 3) * 2;
        float2 y0; y0.x = o[nf][0] * inv0; y0.y = o[nf][1] * inv0;
        float2 y1; y1.x = o[nf][2] * inv1; y1.y = o[nf][3] * inv1;
        *(float2*)(g_y + row0 * EMB + col) = y0;
        *(float2*)(g_y + (row0 + 8) * EMB + col) = y1;
    }
}

// ======================= launch ===============================================
extern "C" void kernel_launch(void* const* d_in, const int* in_sizes, int n_in,
                              void* d_out, int out_size)
{
    const float* x  = (const float*)d_in[0];
    const float* Wa = (const float*)d_in[1];
    const float* ba = (const float*)d_in[2];
    const float* Wo = (const float*)d_in[3];
    const float* bo = (const float*)d_in[4];
    float* out = (float*)d_out;

    cudaFuncSetAttribute(igemm<1>, cudaFuncAttributeMaxDynamicSharedMemorySize, GI_SMEM);
    cudaFuncSetAttribute(igemm<0>, cudaFuncAttributeMaxDynamicSharedMemorySize, GI_SMEM);
    cudaFuncSetAttribute(flash_hmma, cudaFuncAttributeMaxDynamicSharedMemorySize, FA_SMEM);

    __nv_bfloat16 *qh, *ql;
    float *y, *sx, *sy, *swa, *swo;
    int8_t *x1, *x2, *y1, *y2, *wa1, *wa2, *wo1, *wo2;
    cudaGetSymbolAddress((void**)&qh,  g_qkvh);
    cudaGetSymbolAddress((void**)&ql,  g_qkvl);
    cudaGetSymbolAddress((void**)&y,   g_y);
    cudaGetSymbolAddress((void**)&x1,  g_x1);
    cudaGetSymbolAddress((void**)&x2,  g_x2);
    cudaGetSymbolAddress((void**)&sx,  g_sx);
    cudaGetSymbolAddress((void**)&y1,  g_y1);
    cudaGetSymbolAddress((void**)&y2,  g_y2);
    cudaGetSymbolAddress((void**)&sy,  g_sy);
    cudaGetSymbolAddress((void**)&wa1, g_wa1);
    cudaGetSymbolAddress((void**)&wa2, g_wa2);
    cudaGetSymbolAddress((void**)&swa, g_swa);
    cudaGetSymbolAddress((void**)&wo1, g_wo1);
    cudaGetSymbolAddress((void**)&wo2, g_wo2);
    cudaGetSymbolAddress((void**)&swo, g_swo);

    // quantize inputs + weights
    quant_rows<<<MROWS / 8, 256>>>(x, x1, x2, sx);
    wcol_absmax<<<NQKV / 8, 256>>>(Wa, swa, EMB, NQKV);
    wcol_absmax<<<EMB / 8, 256>>>(Wo, swo, EMB, EMB);
    {
        dim3 gt(NQKV / 32, EMB / 32);
        conv_w_tq<<<gt, 256>>>(Wa, wa1, wa2, swa, EMB, NQKV);
        dim3 gt2(EMB / 32, EMB / 32);
        conv_w_tq<<<gt2, 256>>>(Wo, wo1, wo2, swo, EMB, EMB);
    }

    // QKV projection (int8 IMMA) -> bf16 hi/lo for flash
    dim3 g1(NQKV / 128, MROWS / 128);   // (12, 64)
    igemm<1><<<g1, 512, GI_SMEM>>>(x1, x2, sx, wa1, wa2, swa, ba,
                                   nullptr, qh, ql, NQKV, EMB);

    // attention (bf16 split HMMA) -> fp32 y
    dim3 g2(SEQ / 128, HEADS, BATCH);   // (16, 8, 4)
    flash_hmma<<<g2, 256, FA_SMEM>>>();

    // quantize y, output projection (int8 IMMA) -> fp32 out
    quant_rows<<<MROWS / 8, 256>>>(y, y1, y2, sy);
    dim3 g3(EMB / 128, MROWS / 128);    // (4, 64)
    igemm<0><<<g3, 512, GI_SMEM>>>(y1, y2, sy, wo1, wo2, swo, bo,
                                   out, nullptr, nullptr, EMB, EMB);
}